// round 11
// baseline (speedup 1.0000x reference)
#include <cuda_runtime.h>
#include <cuda_fp16.h>
#include <math.h>

#define M_NODES 16384
#define D_DIM   128
#define N_NBR   32
#define H_HEADS 8
#define DH_DIM  16
#define R_REL   237
#define LN_EPS  1e-5f
#define ATT_SCALE 0.25f   // 16^-0.5

#define XT_STRIDE 68   // multiple of 4 (16B-aligned float4 reads), not mult of 32

// ---------------- scratch (static device globals; no allocs allowed) --------
__device__ float  g_Q  [M_NODES * D_DIM];
__device__ __half g_KXh[M_NODES * D_DIM];   // fp16 K table
__device__ __half g_VXh[M_NODES * D_DIM];   // fp16 V table
__device__ float  g_RK [R_REL   * D_DIM];   // fp32 (L1-resident)
__device__ float  g_Att[M_NODES * D_DIM];
__device__ int    g_flags[2];   // [0]=indices are int64, [1]=mask is int32

// ---------------------------------------------------------------------------
// dtype probe: parallel over 1024 threads, block-wide OR reduction.
// ---------------------------------------------------------------------------
__global__ void detect_dtypes(const int* __restrict__ nidx_w,
                              const unsigned char* __restrict__ mask_b)
{
    const int t = threadIdx.x;
    int odd = 0, hi = 0;
    if (t < 256) odd = (nidx_w[2 * t + 1] != 0);
    if ((t & 3) != 0) hi = (mask_b[t] != 0);
    odd = __syncthreads_or(odd);
    hi  = __syncthreads_or(hi);
    if (t == 0) { g_flags[0] = !odd; g_flags[1] = !hi; }
}

// ---------------------------------------------------------------------------
// Fused projection GEMM, 64x128 tiles, 512 threads. grid = (260, 3):
//   y=0, bx<256 : Q  = X @ Wq + bq                (fp32 out)
//   y=1, bx<256 : KXh = X @ Wk                    (fp16 out)
//   y=1, bx>=256: RK = rel @ Wk + bk  (fp32 out; 4 tiles cover 237 rows)
//   y=2, bx<256 : VXh = X @ Wv + bv               (fp16 out)
// Micro-tile 2 rows x 8 cols; k-chunks of 32.
// ---------------------------------------------------------------------------
__global__ __launch_bounds__(512) void gemm_fused(
    const float* __restrict__ X, const float* __restrict__ rel,
    const float* __restrict__ Wq, const float* __restrict__ bq,
    const float* __restrict__ Wk, const float* __restrict__ bk,
    const float* __restrict__ Wv, const float* __restrict__ bv,
    float* __restrict__ Q, __half* __restrict__ KXh,
    __half* __restrict__ VXh, float* __restrict__ RK)
{
    const int bx = blockIdx.x, by = blockIdx.y;
    const float *Xp, *W, *bias;
    int rows, row0, half_out;
    float*  OutF = 0;
    __half* OutH = 0;
    if (by == 0) {
        if (bx >= 256) return;
        Xp = X; W = Wq; bias = bq; OutF = Q; rows = M_NODES; row0 = bx * 64; half_out = 0;
    } else if (by == 2) {
        if (bx >= 256) return;
        Xp = X; W = Wv; bias = bv; OutH = VXh; rows = M_NODES; row0 = bx * 64; half_out = 1;
    } else if (bx < 256) {
        Xp = X; W = Wk; bias = 0;  OutH = KXh; rows = M_NODES; row0 = bx * 64; half_out = 1;
    } else {
        Xp = rel; W = Wk; bias = bk; OutF = RK; rows = R_REL; row0 = (bx - 256) * 64; half_out = 0;
    }

    __shared__ float sXt[32 * XT_STRIDE];  // [k][row]
    __shared__ float sW [32 * 128];        // [k][col]

    const int tid = threadIdx.x;
    const int tx = tid & 15, ty = tid >> 4;   // ty: 0..31

    float acc[2][8];
#pragma unroll
    for (int i = 0; i < 2; i++)
#pragma unroll
        for (int j = 0; j < 8; j++) acc[i][j] = 0.f;

    for (int k0 = 0; k0 < 128; k0 += 32) {
        // W chunk [32][128]: 1024 float4
#pragma unroll
        for (int it = 0; it < 2; it++) {
            int i  = tid + it * 512;
            int kk = i >> 5, cq = i & 31;
            reinterpret_cast<float4*>(&sW[kk * 128])[cq] =
                reinterpret_cast<const float4*>(W + (size_t)(k0 + kk) * 128)[cq];
        }
        // X chunk [64][32] -> transposed sXt[k][row]: 512 float4
        {
            int r  = tid >> 3, kq = tid & 7;
            float4 v = make_float4(0.f, 0.f, 0.f, 0.f);
            if (row0 + r < rows)
                v = reinterpret_cast<const float4*>(Xp + (size_t)(row0 + r) * 128 + k0)[kq];
            sXt[(kq * 4 + 0) * XT_STRIDE + r] = v.x;
            sXt[(kq * 4 + 1) * XT_STRIDE + r] = v.y;
            sXt[(kq * 4 + 2) * XT_STRIDE + r] = v.z;
            sXt[(kq * 4 + 3) * XT_STRIDE + r] = v.w;
        }
        __syncthreads();
#pragma unroll
        for (int kk = 0; kk < 32; kk++) {
            float2 a2 = *reinterpret_cast<const float2*>(&sXt[kk * XT_STRIDE + ty * 2]);
            float4 b0 = *reinterpret_cast<const float4*>(&sW [kk * 128 + tx * 8]);
            float4 b1 = *reinterpret_cast<const float4*>(&sW [kk * 128 + tx * 8 + 4]);
            float a[2] = {a2.x, a2.y};
            float b[8] = {b0.x, b0.y, b0.z, b0.w, b1.x, b1.y, b1.z, b1.w};
#pragma unroll
            for (int i = 0; i < 2; i++)
#pragma unroll
                for (int j = 0; j < 8; j++) acc[i][j] = fmaf(a[i], b[j], acc[i][j]);
        }
        __syncthreads();
    }

    float bb[8];
#pragma unroll
    for (int j = 0; j < 8; j++) bb[j] = bias ? bias[tx * 8 + j] : 0.f;

#pragma unroll
    for (int i = 0; i < 2; i++) {
        int r = row0 + ty * 2 + i;
        if (r < rows) {
            float o[8];
#pragma unroll
            for (int j = 0; j < 8; j++) o[j] = acc[i][j] + bb[j];
            if (half_out) {
                __half2 h0 = __floats2half2_rn(o[0], o[1]);
                __half2 h1 = __floats2half2_rn(o[2], o[3]);
                __half2 h2 = __floats2half2_rn(o[4], o[5]);
                __half2 h3 = __floats2half2_rn(o[6], o[7]);
                uint4 pk;
                pk.x = *reinterpret_cast<unsigned*>(&h0);
                pk.y = *reinterpret_cast<unsigned*>(&h1);
                pk.z = *reinterpret_cast<unsigned*>(&h2);
                pk.w = *reinterpret_cast<unsigned*>(&h3);
                *reinterpret_cast<uint4*>(OutH + (size_t)r * 128 + tx * 8) = pk;
            } else {
                *reinterpret_cast<float4*>(OutF + (size_t)r * 128 + tx * 8)
                    = make_float4(o[0], o[1], o[2], o[3]);
                *reinterpret_cast<float4*>(OutF + (size_t)r * 128 + tx * 8 + 4)
                    = make_float4(o[4], o[5], o[6], o[7]);
            }
        }
    }
}

// ---------------------------------------------------------------------------
// Attention: one WARP per node. Lane j owns dims [4j,4j+4) (head = j>>2).
// K/V gathered from fp16 tables (8B/lane), RK fp32 (L1-resident).
// Scores via dot4 + quad shfl reduction; softmax register-resident.
// ---------------------------------------------------------------------------
__global__ __launch_bounds__(256) void attn_kernel(
    const void* __restrict__ nidx_v, const void* __restrict__ rids_v,
    const void* __restrict__ mask_v)
{
    __shared__ int s_idx[8][32];
    __shared__ int s_rel[8][32];

    const int warp = threadIdx.x >> 5;
    const int lane = threadIdx.x & 31;
    const int m = blockIdx.x * 8 + warp;

    {
        size_t pos = (size_t)m * 32 + lane;
        const int idx64 = g_flags[0];
        const int msk32 = g_flags[1];
        int mk;
        if (msk32) mk = ((const int*)mask_v)[pos] != 0;
        else       mk = ((const unsigned char*)mask_v)[pos] != 0;
        int idx, rel;
        if (idx64) {
            idx = (int)((const long long*)nidx_v)[pos];
            rel = (int)((const long long*)rids_v)[pos];
        } else {
            idx = ((const int*)nidx_v)[pos];
            rel = ((const int*)rids_v)[pos];
        }
        s_idx[warp][lane] = mk ? idx : 0;
        s_rel[warp][lane] = mk ? rel : 0;
    }
    const unsigned mbits = __ballot_sync(0xffffffffu,
        (g_flags[1] ? ((const int*)mask_v)[(size_t)m * 32 + lane]
                    : (int)((const unsigned char*)mask_v)[(size_t)m * 32 + lane]) != 0);
    __syncwarp();

    const float4 q4 = *reinterpret_cast<const float4*>(g_Q + (size_t)m * 128 + lane * 4);

    float sc[32];
#pragma unroll
    for (int n = 0; n < 32; n++) {
        uint2 kraw = *reinterpret_cast<const uint2*>(
            g_KXh + (size_t)s_idx[warp][n] * 128 + lane * 4);
        float4 r4 = *reinterpret_cast<const float4*>(
            g_RK + (size_t)s_rel[warp][n] * 128 + lane * 4);
        float2 k01 = __half22float2(*reinterpret_cast<__half2*>(&kraw.x));
        float2 k23 = __half22float2(*reinterpret_cast<__half2*>(&kraw.y));
        float p = q4.x * (k01.x + r4.x) + q4.y * (k01.y + r4.y)
                + q4.z * (k23.x + r4.z) + q4.w * (k23.y + r4.w);
        p += __shfl_xor_sync(0xffffffffu, p, 1);
        p += __shfl_xor_sync(0xffffffffu, p, 2);
        sc[n] = ((mbits >> n) & 1u) ? p * ATT_SCALE : -1e30f;
    }

    float mx = -1e30f;
#pragma unroll
    for (int n = 0; n < 32; n++) mx = fmaxf(mx, sc[n]);
    float sum = 0.f;
#pragma unroll
    for (int n = 0; n < 32; n++) {
        float e = __expf(sc[n] - mx);
        sc[n] = e;
        sum += e;
    }
    const float inv = 1.f / sum;

    float4 acc = make_float4(0.f, 0.f, 0.f, 0.f);
#pragma unroll
    for (int n = 0; n < 32; n++) {
        float p = sc[n] * inv;
        uint2 vraw = *reinterpret_cast<const uint2*>(
            g_VXh + (size_t)s_idx[warp][n] * 128 + lane * 4);
        float2 v01 = __half22float2(*reinterpret_cast<__half2*>(&vraw.x));
        float2 v23 = __half22float2(*reinterpret_cast<__half2*>(&vraw.y));
        acc.x = fmaf(p, v01.x, acc.x);
        acc.y = fmaf(p, v01.y, acc.y);
        acc.z = fmaf(p, v23.x, acc.z);
        acc.w = fmaf(p, v23.y, acc.w);
    }
    *reinterpret_cast<float4*>(g_Att + (size_t)m * 128 + lane * 4) = acc;
}

// ---------------------------------------------------------------------------
// Out = LN(entity + Att @ Wo + bo). 64x128 tiles, 512 threads, grid 256.
// Micro-tile 2x8; fused LN epilogue.
// ---------------------------------------------------------------------------
__global__ __launch_bounds__(512) void out_ln_kernel(
    const float* __restrict__ Att, const float* __restrict__ Wo,
    const float* __restrict__ bo,  const float* __restrict__ ent,
    const float* __restrict__ gamma, const float* __restrict__ beta,
    float* __restrict__ Out)
{
    __shared__ float sXt[32 * XT_STRIDE];
    __shared__ float sW [32 * 128];

    const int tid = threadIdx.x;
    const int tx = tid & 15, ty = tid >> 4;   // ty: 0..31
    const int row0 = blockIdx.x * 64;

    float acc[2][8];
#pragma unroll
    for (int i = 0; i < 2; i++)
#pragma unroll
        for (int j = 0; j < 8; j++) acc[i][j] = 0.f;

    for (int k0 = 0; k0 < 128; k0 += 32) {
#pragma unroll
        for (int it = 0; it < 2; it++) {
            int i  = tid + it * 512;
            int kk = i >> 5, cq = i & 31;
            reinterpret_cast<float4*>(&sW[kk * 128])[cq] =
                reinterpret_cast<const float4*>(Wo + (size_t)(k0 + kk) * 128)[cq];
        }
        {
            int r  = tid >> 3, kq = tid & 7;
            float4 v = reinterpret_cast<const float4*>(Att + (size_t)(row0 + r) * 128 + k0)[kq];
            sXt[(kq * 4 + 0) * XT_STRIDE + r] = v.x;
            sXt[(kq * 4 + 1) * XT_STRIDE + r] = v.y;
            sXt[(kq * 4 + 2) * XT_STRIDE + r] = v.z;
            sXt[(kq * 4 + 3) * XT_STRIDE + r] = v.w;
        }
        __syncthreads();
#pragma unroll
        for (int kk = 0; kk < 32; kk++) {
            float2 a2 = *reinterpret_cast<const float2*>(&sXt[kk * XT_STRIDE + ty * 2]);
            float4 b0 = *reinterpret_cast<const float4*>(&sW [kk * 128 + tx * 8]);
            float4 b1 = *reinterpret_cast<const float4*>(&sW [kk * 128 + tx * 8 + 4]);
            float a[2] = {a2.x, a2.y};
            float b[8] = {b0.x, b0.y, b0.z, b0.w, b1.x, b1.y, b1.z, b1.w};
#pragma unroll
            for (int i = 0; i < 2; i++)
#pragma unroll
                for (int j = 0; j < 8; j++) acc[i][j] = fmaf(a[i], b[j], acc[i][j]);
        }
        __syncthreads();
    }

    float bb[8], gg[8], be[8];
#pragma unroll
    for (int j = 0; j < 8; j++) {
        int c = tx * 8 + j;
        bb[j] = bo[c]; gg[j] = gamma[c]; be[j] = beta[c];
    }

    float ps[2], pq[2];
#pragma unroll
    for (int i = 0; i < 2; i++) {
        int r = row0 + ty * 2 + i;
        float4 e0 = *reinterpret_cast<const float4*>(ent + (size_t)r * 128 + tx * 8);
        float4 e1 = *reinterpret_cast<const float4*>(ent + (size_t)r * 128 + tx * 8 + 4);
        float ev[8] = {e0.x, e0.y, e0.z, e0.w, e1.x, e1.y, e1.z, e1.w};
        float s1 = 0.f, s2 = 0.f;
#pragma unroll
        for (int j = 0; j < 8; j++) {
            float v = acc[i][j] + bb[j] + ev[j];
            acc[i][j] = v;
            s1 += v;
            s2 = fmaf(v, v, s2);
        }
        ps[i] = s1; pq[i] = s2;
    }

    float* red1 = sXt;               // [64][16] = 1024 floats
    float* red2 = sXt + 1024;        // 2048 <= 32*68=2176, fits
#pragma unroll
    for (int i = 0; i < 2; i++) {
        int rl = ty * 2 + i;
        red1[rl * 16 + tx] = ps[i];
        red2[rl * 16 + tx] = pq[i];
    }
    __syncthreads();

#pragma unroll
    for (int i = 0; i < 2; i++) {
        int rl = ty * 2 + i;
        float s1 = 0.f, s2 = 0.f;
#pragma unroll
        for (int t = 0; t < 16; t++) { s1 += red1[rl * 16 + t]; s2 += red2[rl * 16 + t]; }
        float mu   = s1 * (1.f / 128.f);
        float var  = s2 * (1.f / 128.f) - mu * mu;
        float rstd = rsqrtf(var + LN_EPS);
        int r = row0 + rl;
        float o[8];
#pragma unroll
        for (int j = 0; j < 8; j++)
            o[j] = (acc[i][j] - mu) * rstd * gg[j] + be[j];
        *reinterpret_cast<float4*>(Out + (size_t)r * 128 + tx * 8)     = make_float4(o[0], o[1], o[2], o[3]);
        *reinterpret_cast<float4*>(Out + (size_t)r * 128 + tx * 8 + 4) = make_float4(o[4], o[5], o[6], o[7]);
    }
}

// ---------------------------------------------------------------------------
extern "C" void kernel_launch(void* const* d_in, const int* in_sizes, int n_in,
                              void* d_out, int out_size)
{
    const float* ent  = (const float*)d_in[0];
    const void*  nidx = d_in[1];
    const void*  rids = d_in[2];
    const void*  mask = d_in[3];
    const float* Wq = (const float*)d_in[4];
    const float* bq = (const float*)d_in[5];
    const float* Wk = (const float*)d_in[6];
    const float* bk = (const float*)d_in[7];
    const float* Wv = (const float*)d_in[8];
    const float* bv = (const float*)d_in[9];
    const float* Wo = (const float*)d_in[10];
    const float* bo = (const float*)d_in[11];
    const float* rel_table = (const float*)d_in[12];
    const float* gamma = (const float*)d_in[13];
    const float* beta  = (const float*)d_in[14];
    float* out = (float*)d_out;

    void *pQ, *pKXh, *pVXh, *pRK, *pAtt;
    cudaGetSymbolAddress(&pQ,   g_Q);
    cudaGetSymbolAddress(&pKXh, g_KXh);
    cudaGetSymbolAddress(&pVXh, g_VXh);
    cudaGetSymbolAddress(&pRK,  g_RK);
    cudaGetSymbolAddress(&pAtt, g_Att);

    detect_dtypes<<<1, 1024>>>((const int*)nidx, (const unsigned char*)mask);

    gemm_fused<<<dim3(260, 3), 512>>>(ent, rel_table, Wq, bq, Wk, bk, Wv, bv,
                                      (float*)pQ, (__half*)pKXh, (__half*)pVXh, (float*)pRK);

    attn_kernel<<<M_NODES / 8, 256>>>(nidx, rids, mask);

    out_ln_kernel<<<M_NODES / 64, 512>>>((const float*)pAtt, Wo, bo, ent, gamma, beta, out);
}

// round 12
// speedup vs baseline: 1.5141x; 1.5141x over previous
#include <cuda_runtime.h>
#include <cuda_fp16.h>
#include <math.h>

#define M_NODES 16384
#define D_DIM   128
#define N_NBR   32
#define H_HEADS 8
#define DH_DIM  16
#define R_REL   237
#define LN_EPS  1e-5f
#define ATT_SCALE 0.25f   // 16^-0.5

#define XT_STRIDE 68   // multiple of 4 (16B-aligned float4 reads), not mult of 32

// ---------------- scratch (static device globals; no allocs allowed) --------
__device__ float  g_Q  [M_NODES * D_DIM];
__device__ __half g_KXh[M_NODES * D_DIM];   // fp16 K table
__device__ __half g_VXh[M_NODES * D_DIM];   // fp16 V table
__device__ float  g_RK [R_REL   * D_DIM];   // fp32 (L1/L2-resident)
__device__ float  g_Att[M_NODES * D_DIM];
__device__ int    g_flags[2];   // [0]=indices are int64, [1]=mask is int32

// ---------------------------------------------------------------------------
// dtype probe: parallel over 1024 threads, block-wide OR reduction.
// ---------------------------------------------------------------------------
__global__ void detect_dtypes(const int* __restrict__ nidx_w,
                              const unsigned char* __restrict__ mask_b)
{
    const int t = threadIdx.x;
    int odd = 0, hi = 0;
    if (t < 256) odd = (nidx_w[2 * t + 1] != 0);
    if ((t & 3) != 0) hi = (mask_b[t] != 0);
    odd = __syncthreads_or(odd);
    hi  = __syncthreads_or(hi);
    if (t == 0) { g_flags[0] = !odd; g_flags[1] = !hi; }
}

// ---------------------------------------------------------------------------
// Fused projection GEMM, 64x128 tiles, 256 threads, 4x8 micro-tile.
// grid = (260, 3):
//   y=0, bx<256 : Q   = X @ Wq + bq   (fp32)
//   y=1, bx<256 : KXh = X @ Wk        (fp16)
//   y=1, bx>=256: RK  = rel @ Wk + bk (fp32; 4 tiles cover 237 rows)
//   y=2, bx<256 : VXh = X @ Wv + bv   (fp16)
// ---------------------------------------------------------------------------
__global__ __launch_bounds__(256) void gemm_fused(
    const float* __restrict__ X, const float* __restrict__ rel,
    const float* __restrict__ Wq, const float* __restrict__ bq,
    const float* __restrict__ Wk, const float* __restrict__ bk,
    const float* __restrict__ Wv, const float* __restrict__ bv,
    float* __restrict__ Q, __half* __restrict__ KXh,
    __half* __restrict__ VXh, float* __restrict__ RK)
{
    const int bx = blockIdx.x, by = blockIdx.y;
    const float *Xp, *W, *bias;
    int rows, row0, half_out;
    float*  OutF = 0;
    __half* OutH = 0;
    if (by == 0) {
        if (bx >= 256) return;
        Xp = X; W = Wq; bias = bq; OutF = Q; rows = M_NODES; row0 = bx * 64; half_out = 0;
    } else if (by == 2) {
        if (bx >= 256) return;
        Xp = X; W = Wv; bias = bv; OutH = VXh; rows = M_NODES; row0 = bx * 64; half_out = 1;
    } else if (bx < 256) {
        Xp = X; W = Wk; bias = 0;  OutH = KXh; rows = M_NODES; row0 = bx * 64; half_out = 1;
    } else {
        Xp = rel; W = Wk; bias = bk; OutF = RK; rows = R_REL; row0 = (bx - 256) * 64; half_out = 0;
    }

    __shared__ float sXt[32 * XT_STRIDE];  // [k][row]
    __shared__ float sW [32 * 128];        // [k][col]

    const int tid = threadIdx.x;
    const int tx = tid & 15, ty = tid >> 4;   // ty: 0..15

    float acc[4][8];
#pragma unroll
    for (int i = 0; i < 4; i++)
#pragma unroll
        for (int j = 0; j < 8; j++) acc[i][j] = 0.f;

    for (int k0 = 0; k0 < 128; k0 += 32) {
        // W chunk [32][128]: 1024 float4, coalesced
#pragma unroll
        for (int it = 0; it < 4; it++) {
            int i  = tid + it * 256;
            int kk = i >> 5, cq = i & 31;
            reinterpret_cast<float4*>(&sW[kk * 128])[cq] =
                reinterpret_cast<const float4*>(W + (size_t)(k0 + kk) * 128)[cq];
        }
        // X chunk [64][32] -> transposed sXt[k][row]: 512 float4
#pragma unroll
        for (int it = 0; it < 2; it++) {
            int i  = tid + it * 256;
            int r  = i >> 3, kq = i & 7;
            float4 v = make_float4(0.f, 0.f, 0.f, 0.f);
            if (row0 + r < rows)
                v = reinterpret_cast<const float4*>(Xp + (size_t)(row0 + r) * 128 + k0)[kq];
            sXt[(kq * 4 + 0) * XT_STRIDE + r] = v.x;
            sXt[(kq * 4 + 1) * XT_STRIDE + r] = v.y;
            sXt[(kq * 4 + 2) * XT_STRIDE + r] = v.z;
            sXt[(kq * 4 + 3) * XT_STRIDE + r] = v.w;
        }
        __syncthreads();
#pragma unroll
        for (int kk = 0; kk < 32; kk++) {
            float4 a4 = *reinterpret_cast<const float4*>(&sXt[kk * XT_STRIDE + ty * 4]);
            float4 b0 = *reinterpret_cast<const float4*>(&sW [kk * 128 + tx * 8]);
            float4 b1 = *reinterpret_cast<const float4*>(&sW [kk * 128 + tx * 8 + 4]);
            float a[4] = {a4.x, a4.y, a4.z, a4.w};
            float b[8] = {b0.x, b0.y, b0.z, b0.w, b1.x, b1.y, b1.z, b1.w};
#pragma unroll
            for (int i = 0; i < 4; i++)
#pragma unroll
                for (int j = 0; j < 8; j++) acc[i][j] = fmaf(a[i], b[j], acc[i][j]);
        }
        __syncthreads();
    }

    float bb[8];
#pragma unroll
    for (int j = 0; j < 8; j++) bb[j] = bias ? bias[tx * 8 + j] : 0.f;

#pragma unroll
    for (int i = 0; i < 4; i++) {
        int r = row0 + ty * 4 + i;
        if (r < rows) {
            float o[8];
#pragma unroll
            for (int j = 0; j < 8; j++) o[j] = acc[i][j] + bb[j];
            if (half_out) {
                __half2 h0 = __floats2half2_rn(o[0], o[1]);
                __half2 h1 = __floats2half2_rn(o[2], o[3]);
                __half2 h2 = __floats2half2_rn(o[4], o[5]);
                __half2 h3 = __floats2half2_rn(o[6], o[7]);
                uint4 pk;
                pk.x = *reinterpret_cast<unsigned*>(&h0);
                pk.y = *reinterpret_cast<unsigned*>(&h1);
                pk.z = *reinterpret_cast<unsigned*>(&h2);
                pk.w = *reinterpret_cast<unsigned*>(&h3);
                *reinterpret_cast<uint4*>(OutH + (size_t)r * 128 + tx * 8) = pk;
            } else {
                *reinterpret_cast<float4*>(OutF + (size_t)r * 128 + tx * 8)
                    = make_float4(o[0], o[1], o[2], o[3]);
                *reinterpret_cast<float4*>(OutF + (size_t)r * 128 + tx * 8 + 4)
                    = make_float4(o[4], o[5], o[6], o[7]);
            }
        }
    }
}

// ---------------------------------------------------------------------------
// Attention: one WARP per node. Lane j owns dims [4j,4j+4) (head = j>>2).
// K/V gathered from fp16 tables (8B/lane), RK fp32.
// Scores via dot4 + quad shfl reduction; softmax register-resident.
// ---------------------------------------------------------------------------
__global__ __launch_bounds__(256) void attn_kernel(
    const void* __restrict__ nidx_v, const void* __restrict__ rids_v,
    const void* __restrict__ mask_v)
{
    __shared__ int s_idx[8][32];
    __shared__ int s_rel[8][32];

    const int warp = threadIdx.x >> 5;
    const int lane = threadIdx.x & 31;
    const int m = blockIdx.x * 8 + warp;

    {
        size_t pos = (size_t)m * 32 + lane;
        const int idx64 = g_flags[0];
        const int msk32 = g_flags[1];
        int mk;
        if (msk32) mk = ((const int*)mask_v)[pos] != 0;
        else       mk = ((const unsigned char*)mask_v)[pos] != 0;
        int idx, rel;
        if (idx64) {
            idx = (int)((const long long*)nidx_v)[pos];
            rel = (int)((const long long*)rids_v)[pos];
        } else {
            idx = ((const int*)nidx_v)[pos];
            rel = ((const int*)rids_v)[pos];
        }
        s_idx[warp][lane] = mk ? idx : 0;
        s_rel[warp][lane] = mk ? rel : 0;
    }
    const unsigned mbits = __ballot_sync(0xffffffffu,
        (g_flags[1] ? ((const int*)mask_v)[(size_t)m * 32 + lane]
                    : (int)((const unsigned char*)mask_v)[(size_t)m * 32 + lane]) != 0);
    __syncwarp();

    const float4 q4 = *reinterpret_cast<const float4*>(g_Q + (size_t)m * 128 + lane * 4);

    float sc[32];
#pragma unroll
    for (int n = 0; n < 32; n++) {
        uint2 kraw = *reinterpret_cast<const uint2*>(
            g_KXh + (size_t)s_idx[warp][n] * 128 + lane * 4);
        float4 r4 = *reinterpret_cast<const float4*>(
            g_RK + (size_t)s_rel[warp][n] * 128 + lane * 4);
        float2 k01 = __half22float2(*reinterpret_cast<__half2*>(&kraw.x));
        float2 k23 = __half22float2(*reinterpret_cast<__half2*>(&kraw.y));
        float p = q4.x * (k01.x + r4.x) + q4.y * (k01.y + r4.y)
                + q4.z * (k23.x + r4.z) + q4.w * (k23.y + r4.w);
        p += __shfl_xor_sync(0xffffffffu, p, 1);
        p += __shfl_xor_sync(0xffffffffu, p, 2);
        sc[n] = ((mbits >> n) & 1u) ? p * ATT_SCALE : -1e30f;
    }

    float mx = -1e30f;
#pragma unroll
    for (int n = 0; n < 32; n++) mx = fmaxf(mx, sc[n]);
    float sum = 0.f;
#pragma unroll
    for (int n = 0; n < 32; n++) {
        float e = __expf(sc[n] - mx);
        sc[n] = e;
        sum += e;
    }
    const float inv = 1.f / sum;

    float4 acc = make_float4(0.f, 0.f, 0.f, 0.f);
#pragma unroll
    for (int n = 0; n < 32; n++) {
        float p = sc[n] * inv;
        uint2 vraw = *reinterpret_cast<const uint2*>(
            g_VXh + (size_t)s_idx[warp][n] * 128 + lane * 4);
        float2 v01 = __half22float2(*reinterpret_cast<__half2*>(&vraw.x));
        float2 v23 = __half22float2(*reinterpret_cast<__half2*>(&vraw.y));
        acc.x = fmaf(p, v01.x, acc.x);
        acc.y = fmaf(p, v01.y, acc.y);
        acc.z = fmaf(p, v23.x, acc.z);
        acc.w = fmaf(p, v23.y, acc.w);
    }
    *reinterpret_cast<float4*>(g_Att + (size_t)m * 128 + lane * 4) = acc;
}

// ---------------------------------------------------------------------------
// Out = LN(entity + Att @ Wo + bo). 64x128 tiles, 256 threads, 4x8 micro-tile,
// grid 256; fused LN epilogue.
// ---------------------------------------------------------------------------
__global__ __launch_bounds__(256) void out_ln_kernel(
    const float* __restrict__ Att, const float* __restrict__ Wo,
    const float* __restrict__ bo,  const float* __restrict__ ent,
    const float* __restrict__ gamma, const float* __restrict__ beta,
    float* __restrict__ Out)
{
    __shared__ float sXt[32 * XT_STRIDE];
    __shared__ float sW [32 * 128];

    const int tid = threadIdx.x;
    const int tx = tid & 15, ty = tid >> 4;
    const int row0 = blockIdx.x * 64;

    float acc[4][8];
#pragma unroll
    for (int i = 0; i < 4; i++)
#pragma unroll
        for (int j = 0; j < 8; j++) acc[i][j] = 0.f;

    for (int k0 = 0; k0 < 128; k0 += 32) {
#pragma unroll
        for (int it = 0; it < 4; it++) {
            int i  = tid + it * 256;
            int kk = i >> 5, cq = i & 31;
            reinterpret_cast<float4*>(&sW[kk * 128])[cq] =
                reinterpret_cast<const float4*>(Wo + (size_t)(k0 + kk) * 128)[cq];
        }
#pragma unroll
        for (int it = 0; it < 2; it++) {
            int i  = tid + it * 256;
            int r  = i >> 3, kq = i & 7;
            float4 v = reinterpret_cast<const float4*>(Att + (size_t)(row0 + r) * 128 + k0)[kq];
            sXt[(kq * 4 + 0) * XT_STRIDE + r] = v.x;
            sXt[(kq * 4 + 1) * XT_STRIDE + r] = v.y;
            sXt[(kq * 4 + 2) * XT_STRIDE + r] = v.z;
            sXt[(kq * 4 + 3) * XT_STRIDE + r] = v.w;
        }
        __syncthreads();
#pragma unroll
        for (int kk = 0; kk < 32; kk++) {
            float4 a4 = *reinterpret_cast<const float4*>(&sXt[kk * XT_STRIDE + ty * 4]);
            float4 b0 = *reinterpret_cast<const float4*>(&sW [kk * 128 + tx * 8]);
            float4 b1 = *reinterpret_cast<const float4*>(&sW [kk * 128 + tx * 8 + 4]);
            float a[4] = {a4.x, a4.y, a4.z, a4.w};
            float b[8] = {b0.x, b0.y, b0.z, b0.w, b1.x, b1.y, b1.z, b1.w};
#pragma unroll
            for (int i = 0; i < 4; i++)
#pragma unroll
                for (int j = 0; j < 8; j++) acc[i][j] = fmaf(a[i], b[j], acc[i][j]);
        }
        __syncthreads();
    }

    float bb[8], gg[8], be[8];
#pragma unroll
    for (int j = 0; j < 8; j++) {
        int c = tx * 8 + j;
        bb[j] = bo[c]; gg[j] = gamma[c]; be[j] = beta[c];
    }

    float ps[4], pq[4];
#pragma unroll
    for (int i = 0; i < 4; i++) {
        int r = row0 + ty * 4 + i;
        float4 e0 = *reinterpret_cast<const float4*>(ent + (size_t)r * 128 + tx * 8);
        float4 e1 = *reinterpret_cast<const float4*>(ent + (size_t)r * 128 + tx * 8 + 4);
        float ev[8] = {e0.x, e0.y, e0.z, e0.w, e1.x, e1.y, e1.z, e1.w};
        float s1 = 0.f, s2 = 0.f;
#pragma unroll
        for (int j = 0; j < 8; j++) {
            float v = acc[i][j] + bb[j] + ev[j];
            acc[i][j] = v;
            s1 += v;
            s2 = fmaf(v, v, s2);
        }
        ps[i] = s1; pq[i] = s2;
    }

    float* red1 = sXt;               // [64][16] = 1024 floats
    float* red2 = sXt + 1024;        // 2048 <= 32*68=2176, fits
#pragma unroll
    for (int i = 0; i < 4; i++) {
        int rl = ty * 4 + i;
        red1[rl * 16 + tx] = ps[i];
        red2[rl * 16 + tx] = pq[i];
    }
    __syncthreads();

#pragma unroll
    for (int i = 0; i < 4; i++) {
        int rl = ty * 4 + i;
        float s1 = 0.f, s2 = 0.f;
#pragma unroll
        for (int t = 0; t < 16; t++) { s1 += red1[rl * 16 + t]; s2 += red2[rl * 16 + t]; }
        float mu   = s1 * (1.f / 128.f);
        float var  = s2 * (1.f / 128.f) - mu * mu;
        float rstd = rsqrtf(var + LN_EPS);
        int r = row0 + rl;
        float o[8];
#pragma unroll
        for (int j = 0; j < 8; j++)
            o[j] = (acc[i][j] - mu) * rstd * gg[j] + be[j];
        *reinterpret_cast<float4*>(Out + (size_t)r * 128 + tx * 8)     = make_float4(o[0], o[1], o[2], o[3]);
        *reinterpret_cast<float4*>(Out + (size_t)r * 128 + tx * 8 + 4) = make_float4(o[4], o[5], o[6], o[7]);
    }
}

// ---------------------------------------------------------------------------
extern "C" void kernel_launch(void* const* d_in, const int* in_sizes, int n_in,
                              void* d_out, int out_size)
{
    const float* ent  = (const float*)d_in[0];
    const void*  nidx = d_in[1];
    const void*  rids = d_in[2];
    const void*  mask = d_in[3];
    const float* Wq = (const float*)d_in[4];
    const float* bq = (const float*)d_in[5];
    const float* Wk = (const float*)d_in[6];
    const float* bk = (const float*)d_in[7];
    const float* Wv = (const float*)d_in[8];
    const float* bv = (const float*)d_in[9];
    const float* Wo = (const float*)d_in[10];
    const float* bo = (const float*)d_in[11];
    const float* rel_table = (const float*)d_in[12];
    const float* gamma = (const float*)d_in[13];
    const float* beta  = (const float*)d_in[14];
    float* out = (float*)d_out;

    void *pQ, *pKXh, *pVXh, *pRK, *pAtt;
    cudaGetSymbolAddress(&pQ,   g_Q);
    cudaGetSymbolAddress(&pKXh, g_KXh);
    cudaGetSymbolAddress(&pVXh, g_VXh);
    cudaGetSymbolAddress(&pRK,  g_RK);
    cudaGetSymbolAddress(&pAtt, g_Att);

    detect_dtypes<<<1, 1024>>>((const int*)nidx, (const unsigned char*)mask);

    gemm_fused<<<dim3(260, 3), 256>>>(ent, rel_table, Wq, bq, Wk, bk, Wv, bv,
                                      (float*)pQ, (__half*)pKXh, (__half*)pVXh, (float*)pRK);

    attn_kernel<<<M_NODES / 8, 256>>>(nidx, rids, mask);

    out_ln_kernel<<<M_NODES / 64, 256>>>((const float*)pAtt, Wo, bo, ent, gamma, beta, out);
}

// round 14
// speedup vs baseline: 1.8345x; 1.2117x over previous
#include <cuda_runtime.h>
#include <cuda_fp16.h>
#include <mma.h>
#include <math.h>

using namespace nvcuda;

#define M_NODES 16384
#define D_DIM   128
#define N_NBR   32
#define H_HEADS 8
#define DH_DIM  16
#define R_REL   237
#define R_PAD   256
#define LN_EPS  1e-5f
#define ATT_SCALE 0.25f   // 16^-0.5

#define XT_STRIDE 68   // multiple of 4 (16B-aligned float4 reads), not mult of 32

// ---------------- scratch (static device globals; no allocs allowed) --------
__device__ float  g_Q  [M_NODES * D_DIM];
__device__ __half g_KXh[M_NODES * D_DIM];   // fp16 K table
__device__ __half g_VXh[M_NODES * D_DIM];   // fp16 V table
__device__ float  g_RK [R_REL   * D_DIM];   // fp32
__device__ float  g_Att[M_NODES * D_DIM];
__device__ __half g_Xh  [M_NODES * D_DIM];  // fp16 copy of entity_repr
__device__ __half g_relh[R_PAD  * D_DIM];   // fp16 rel_table (zero-padded)
__device__ __half g_Wqh[D_DIM * D_DIM];
__device__ __half g_Wkh[D_DIM * D_DIM];
__device__ __half g_Wvh[D_DIM * D_DIM];
__device__ int    g_flags[2];   // [0]=indices are int64, [1]=mask is int32

// ---------------------------------------------------------------------------
// dtype probe: parallel over 1024 threads, block-wide OR reduction.
// ---------------------------------------------------------------------------
__global__ void detect_dtypes(const int* __restrict__ nidx_w,
                              const unsigned char* __restrict__ mask_b)
{
    const int t = threadIdx.x;
    int odd = 0, hi = 0;
    if (t < 256) odd = (nidx_w[2 * t + 1] != 0);
    if ((t & 3) != 0) hi = (mask_b[t] != 0);
    odd = __syncthreads_or(odd);
    hi  = __syncthreads_or(hi);
    if (t == 0) { g_flags[0] = !odd; g_flags[1] = !hi; }
}

// ---------------------------------------------------------------------------
// fp32 -> fp16 conversion prep. Each block converts 2048 elements.
// Segments: X (1024 blocks), rel padded (16), Wq (8), Wk (8), Wv (8).
// ---------------------------------------------------------------------------
__global__ __launch_bounds__(256) void convert_prep(
    const float* __restrict__ X, const float* __restrict__ rel,
    const float* __restrict__ Wq, const float* __restrict__ Wk,
    const float* __restrict__ Wv)
{
    const int b = blockIdx.x;
    const int t = threadIdx.x;
    const float* src; __half* dst; size_t base, limit;
    if (b < 1024)      { src = X;   dst = g_Xh;   base = (size_t)b * 2048;          limit = (size_t)M_NODES * 128; }
    else if (b < 1040) { src = rel; dst = g_relh; base = (size_t)(b - 1024) * 2048; limit = (size_t)R_REL * 128; }
    else if (b < 1048) { src = Wq;  dst = g_Wqh;  base = (size_t)(b - 1040) * 2048; limit = 16384; }
    else if (b < 1056) { src = Wk;  dst = g_Wkh;  base = (size_t)(b - 1048) * 2048; limit = 16384; }
    else               { src = Wv;  dst = g_Wvh;  base = (size_t)(b - 1056) * 2048; limit = 16384; }

    size_t i = base + (size_t)t * 8;
    float v[8];
#pragma unroll
    for (int j = 0; j < 8; j++)
        v[j] = (i + j < limit) ? src[i + j] : 0.f;
    __half2 h0 = __floats2half2_rn(v[0], v[1]);
    __half2 h1 = __floats2half2_rn(v[2], v[3]);
    __half2 h2 = __floats2half2_rn(v[4], v[5]);
    __half2 h3 = __floats2half2_rn(v[6], v[7]);
    uint4 pk;
    pk.x = *reinterpret_cast<unsigned*>(&h0);
    pk.y = *reinterpret_cast<unsigned*>(&h1);
    pk.z = *reinterpret_cast<unsigned*>(&h2);
    pk.w = *reinterpret_cast<unsigned*>(&h3);
    *reinterpret_cast<uint4*>(dst + i) = pk;
}

// ---------------------------------------------------------------------------
// Tensor-core projection GEMM (wmma HMMA, fp16 in, fp32 accum).
// 64x128 tile per block, 256 threads = 8 warps (2 row x 4 col), each warp
// computes 32x32 via 2x2 16x16x16 fragments. Fragments loaded directly from
// global (L2-resident). grid = (260, 3):
//   y=0, bx<256 : Q   = Xh @ Wqh + bq   (fp32)
//   y=1, bx<256 : KXh = Xh @ Wkh        (fp16)
//   y=1, bx>=256: RK  = relh @ Wkh + bk (fp32; rel padded to 256 rows)
//   y=2, bx<256 : VXh = Xh @ Wvh + bv   (fp16)
// ---------------------------------------------------------------------------
__global__ __launch_bounds__(256) void gemm_tc(
    const float* __restrict__ bq, const float* __restrict__ bk,
    const float* __restrict__ bv,
    float* __restrict__ Q, __half* __restrict__ KXh,
    __half* __restrict__ VXh, float* __restrict__ RK)
{
    const int bx = blockIdx.x, by = blockIdx.y;
    const __half *A, *W;
    const float* bias;
    float*  OutF = 0;
    __half* OutH = 0;
    int rows, row0, half_out;
    if (by == 0) {
        if (bx >= 256) return;
        A = g_Xh; W = g_Wqh; bias = bq; OutF = Q; rows = M_NODES; row0 = bx * 64; half_out = 0;
    } else if (by == 2) {
        if (bx >= 256) return;
        A = g_Xh; W = g_Wvh; bias = bv; OutH = VXh; rows = M_NODES; row0 = bx * 64; half_out = 1;
    } else if (bx < 256) {
        A = g_Xh; W = g_Wkh; bias = 0; OutH = KXh; rows = M_NODES; row0 = bx * 64; half_out = 1;
    } else {
        A = g_relh; W = g_Wkh; bias = bk; OutF = RK; rows = R_REL; row0 = (bx - 256) * 64; half_out = 0;
    }

    __shared__ float sOut[64 * 136];

    const int warp = threadIdx.x >> 5;
    const int rw = warp >> 2;    // 0..1 : 32-row band
    const int cw = warp & 3;     // 0..3 : 32-col band

    wmma::fragment<wmma::accumulator, 16, 16, 16, float> c[2][2];
#pragma unroll
    for (int i = 0; i < 2; i++)
#pragma unroll
        for (int j = 0; j < 2; j++) wmma::fill_fragment(c[i][j], 0.f);

#pragma unroll
    for (int k = 0; k < 8; k++) {
        wmma::fragment<wmma::matrix_a, 16, 16, 16, __half, wmma::row_major> a[2];
        wmma::fragment<wmma::matrix_b, 16, 16, 16, __half, wmma::row_major> bfr[2];
#pragma unroll
        for (int i = 0; i < 2; i++)
            wmma::load_matrix_sync(a[i],
                A + (size_t)(row0 + rw * 32 + i * 16) * 128 + k * 16, 128);
#pragma unroll
        for (int j = 0; j < 2; j++)
            wmma::load_matrix_sync(bfr[j],
                W + (size_t)(k * 16) * 128 + cw * 32 + j * 16, 128);
#pragma unroll
        for (int i = 0; i < 2; i++)
#pragma unroll
            for (int j = 0; j < 2; j++)
                wmma::mma_sync(c[i][j], a[i], bfr[j], c[i][j]);
    }

#pragma unroll
    for (int i = 0; i < 2; i++)
#pragma unroll
        for (int j = 0; j < 2; j++)
            wmma::store_matrix_sync(
                sOut + (size_t)(rw * 32 + i * 16) * 136 + cw * 32 + j * 16,
                c[i][j], 136, wmma::mem_row_major);
    __syncthreads();

    // epilogue: 256 threads; thread t handles row t>>2, cols [(t&3)*32, +32)
    {
        const int t = threadIdx.x;
        const int rl = t >> 2;
        const int c0 = (t & 3) * 32;
        const int r = row0 + rl;
        if (r < rows) {
            if (half_out) {
#pragma unroll
                for (int cc = 0; cc < 32; cc += 8) {
                    float o[8];
#pragma unroll
                    for (int u = 0; u < 8; u++) {
                        o[u] = sOut[rl * 136 + c0 + cc + u];
                        if (bias) o[u] += bias[c0 + cc + u];
                    }
                    __half2 h0 = __floats2half2_rn(o[0], o[1]);
                    __half2 h1 = __floats2half2_rn(o[2], o[3]);
                    __half2 h2 = __floats2half2_rn(o[4], o[5]);
                    __half2 h3 = __floats2half2_rn(o[6], o[7]);
                    uint4 pk;
                    pk.x = *reinterpret_cast<unsigned*>(&h0);
                    pk.y = *reinterpret_cast<unsigned*>(&h1);
                    pk.z = *reinterpret_cast<unsigned*>(&h2);
                    pk.w = *reinterpret_cast<unsigned*>(&h3);
                    *reinterpret_cast<uint4*>(OutH + (size_t)r * 128 + c0 + cc) = pk;
                }
            } else {
#pragma unroll
                for (int cc = 0; cc < 32; cc += 4) {
                    float o[4];
#pragma unroll
                    for (int u = 0; u < 4; u++) {
                        o[u] = sOut[rl * 136 + c0 + cc + u];
                        if (bias) o[u] += bias[c0 + cc + u];
                    }
                    *reinterpret_cast<float4*>(OutF + (size_t)r * 128 + c0 + cc)
                        = make_float4(o[0], o[1], o[2], o[3]);
                }
            }
        }
    }
}

// ---------------------------------------------------------------------------
// Attention: one WARP per node. Lane j owns dims [4j,4j+4) (head = j>>2).
// K/V gathered from fp16 tables (8B/lane), RK fp32.
// ---------------------------------------------------------------------------
__global__ __launch_bounds__(256) void attn_kernel(
    const void* __restrict__ nidx_v, const void* __restrict__ rids_v,
    const void* __restrict__ mask_v)
{
    __shared__ int s_idx[8][32];
    __shared__ int s_rel[8][32];

    const int warp = threadIdx.x >> 5;
    const int lane = threadIdx.x & 31;
    const int m = blockIdx.x * 8 + warp;

    {
        size_t pos = (size_t)m * 32 + lane;
        const int idx64 = g_flags[0];
        const int msk32 = g_flags[1];
        int mk;
        if (msk32) mk = ((const int*)mask_v)[pos] != 0;
        else       mk = ((const unsigned char*)mask_v)[pos] != 0;
        int idx, rel;
        if (idx64) {
            idx = (int)((const long long*)nidx_v)[pos];
            rel = (int)((const long long*)rids_v)[pos];
        } else {
            idx = ((const int*)nidx_v)[pos];
            rel = ((const int*)rids_v)[pos];
        }
        s_idx[warp][lane] = mk ? idx : 0;
        s_rel[warp][lane] = mk ? rel : 0;
    }
    const unsigned mbits = __ballot_sync(0xffffffffu,
        (g_flags[1] ? ((const int*)mask_v)[(size_t)m * 32 + lane]
                    : (int)((const unsigned char*)mask_v)[(size_t)m * 32 + lane]) != 0);
    __syncwarp();

    const float4 q4 = *reinterpret_cast<const float4*>(g_Q + (size_t)m * 128 + lane * 4);

    float sc[32];
#pragma unroll
    for (int n = 0; n < 32; n++) {
        uint2 kraw = *reinterpret_cast<const uint2*>(
            g_KXh + (size_t)s_idx[warp][n] * 128 + lane * 4);
        float4 r4 = *reinterpret_cast<const float4*>(
            g_RK + (size_t)s_rel[warp][n] * 128 + lane * 4);
        float2 k01 = __half22float2(*reinterpret_cast<__half2*>(&kraw.x));
        float2 k23 = __half22float2(*reinterpret_cast<__half2*>(&kraw.y));
        float p = q4.x * (k01.x + r4.x) + q4.y * (k01.y + r4.y)
                + q4.z * (k23.x + r4.z) + q4.w * (k23.y + r4.w);
        p += __shfl_xor_sync(0xffffffffu, p, 1);
        p += __shfl_xor_sync(0xffffffffu, p, 2);
        sc[n] = ((mbits >> n) & 1u) ? p * ATT_SCALE : -1e30f;
    }

    float mx = -1e30f;
#pragma unroll
    for (int n = 0; n < 32; n++) mx = fmaxf(mx, sc[n]);
    float sum = 0.f;
#pragma unroll
    for (int n = 0; n < 32; n++) {
        float e = __expf(sc[n] - mx);
        sc[n] = e;
        sum += e;
    }
    const float inv = 1.f / sum;

    float4 acc = make_float4(0.f, 0.f, 0.f, 0.f);
#pragma unroll
    for (int n = 0; n < 32; n++) {
        float p = sc[n] * inv;
        uint2 vraw = *reinterpret_cast<const uint2*>(
            g_VXh + (size_t)s_idx[warp][n] * 128 + lane * 4);
        float2 v01 = __half22float2(*reinterpret_cast<__half2*>(&vraw.x));
        float2 v23 = __half22float2(*reinterpret_cast<__half2*>(&vraw.y));
        acc.x = fmaf(p, v01.x, acc.x);
        acc.y = fmaf(p, v01.y, acc.y);
        acc.z = fmaf(p, v23.x, acc.z);
        acc.w = fmaf(p, v23.y, acc.w);
    }
    *reinterpret_cast<float4*>(g_Att + (size_t)m * 128 + lane * 4) = acc;
}

// ---------------------------------------------------------------------------
// Out = LN(entity + Att @ Wo + bo). 64x128 tiles, 256 threads, 4x8 micro-tile,
// grid 256; fused LN epilogue. (fp32 FFMA — keeps error budget.)
// ---------------------------------------------------------------------------
__global__ __launch_bounds__(256) void out_ln_kernel(
    const float* __restrict__ Att, const float* __restrict__ Wo,
    const float* __restrict__ bo,  const float* __restrict__ ent,
    const float* __restrict__ gamma, const float* __restrict__ beta,
    float* __restrict__ Out)
{
    __shared__ float sXt[32 * XT_STRIDE];
    __shared__ float sW [32 * 128];

    const int tid = threadIdx.x;
    const int tx = tid & 15, ty = tid >> 4;
    const int row0 = blockIdx.x * 64;

    float acc[4][8];
#pragma unroll
    for (int i = 0; i < 4; i++)
#pragma unroll
        for (int j = 0; j < 8; j++) acc[i][j] = 0.f;

    for (int k0 = 0; k0 < 128; k0 += 32) {
#pragma unroll
        for (int it = 0; it < 4; it++) {
            int i  = tid + it * 256;
            int kk = i >> 5, cq = i & 31;
            reinterpret_cast<float4*>(&sW[kk * 128])[cq] =
                reinterpret_cast<const float4*>(Wo + (size_t)(k0 + kk) * 128)[cq];
        }
#pragma unroll
        for (int it = 0; it < 2; it++) {
            int i  = tid + it * 256;
            int r  = i >> 3, kq = i & 7;
            float4 v = reinterpret_cast<const float4*>(Att + (size_t)(row0 + r) * 128 + k0)[kq];
            sXt[(kq * 4 + 0) * XT_STRIDE + r] = v.x;
            sXt[(kq * 4 + 1) * XT_STRIDE + r] = v.y;
            sXt[(kq * 4 + 2) * XT_STRIDE + r] = v.z;
            sXt[(kq * 4 + 3) * XT_STRIDE + r] = v.w;
        }
        __syncthreads();
#pragma unroll
        for (int kk = 0; kk < 32; kk++) {
            float4 a4 = *reinterpret_cast<const float4*>(&sXt[kk * XT_STRIDE + ty * 4]);
            float4 b0 = *reinterpret_cast<const float4*>(&sW [kk * 128 + tx * 8]);
            float4 b1 = *reinterpret_cast<const float4*>(&sW [kk * 128 + tx * 8 + 4]);
            float a[4] = {a4.x, a4.y, a4.z, a4.w};
            float b[8] = {b0.x, b0.y, b0.z, b0.w, b1.x, b1.y, b1.z, b1.w};
#pragma unroll
            for (int i = 0; i < 4; i++)
#pragma unroll
                for (int j = 0; j < 8; j++) acc[i][j] = fmaf(a[i], b[j], acc[i][j]);
        }
        __syncthreads();
    }

    float bb[8], gg[8], be[8];
#pragma unroll
    for (int j = 0; j < 8; j++) {
        int c = tx * 8 + j;
        bb[j] = bo[c]; gg[j] = gamma[c]; be[j] = beta[c];
    }

    float ps[4], pq[4];
#pragma unroll
    for (int i = 0; i < 4; i++) {
        int r = row0 + ty * 4 + i;
        float4 e0 = *reinterpret_cast<const float4*>(ent + (size_t)r * 128 + tx * 8);
        float4 e1 = *reinterpret_cast<const float4*>(ent + (size_t)r * 128 + tx * 8 + 4);
        float ev[8] = {e0.x, e0.y, e0.z, e0.w, e1.x, e1.y, e1.z, e1.w};
        float s1 = 0.f, s2 = 0.f;
#pragma unroll
        for (int j = 0; j < 8; j++) {
            float v = acc[i][j] + bb[j] + ev[j];
            acc[i][j] = v;
            s1 += v;
            s2 = fmaf(v, v, s2);
        }
        ps[i] = s1; pq[i] = s2;
    }

    float* red1 = sXt;               // [64][16] = 1024 floats
    float* red2 = sXt + 1024;        // 2048 <= 32*68=2176, fits
#pragma unroll
    for (int i = 0; i < 4; i++) {
        int rl = ty * 4 + i;
        red1[rl * 16 + tx] = ps[i];
        red2[rl * 16 + tx] = pq[i];
    }
    __syncthreads();

#pragma unroll
    for (int i = 0; i < 4; i++) {
        int rl = ty * 4 + i;
        float s1 = 0.f, s2 = 0.f;
#pragma unroll
        for (int t = 0; t < 16; t++) { s1 += red1[rl * 16 + t]; s2 += red2[rl * 16 + t]; }
        float mu   = s1 * (1.f / 128.f);
        float var  = s2 * (1.f / 128.f) - mu * mu;
        float rstd = rsqrtf(var + LN_EPS);
        int r = row0 + rl;
        float o[8];
#pragma unroll
        for (int j = 0; j < 8; j++)
            o[j] = (acc[i][j] - mu) * rstd * gg[j] + be[j];
        *reinterpret_cast<float4*>(Out + (size_t)r * 128 + tx * 8)     = make_float4(o[0], o[1], o[2], o[3]);
        *reinterpret_cast<float4*>(Out + (size_t)r * 128 + tx * 8 + 4) = make_float4(o[4], o[5], o[6], o[7]);
    }
}

// ---------------------------------------------------------------------------
extern "C" void kernel_launch(void* const* d_in, const int* in_sizes, int n_in,
                              void* d_out, int out_size)
{
    const float* ent  = (const float*)d_in[0];
    const void*  nidx = d_in[1];
    const void*  rids = d_in[2];
    const void*  mask = d_in[3];
    const float* Wq = (const float*)d_in[4];
    const float* bq = (const float*)d_in[5];
    const float* Wk = (const float*)d_in[6];
    const float* bk = (const float*)d_in[7];
    const float* Wv = (const float*)d_in[8];
    const float* bv = (const float*)d_in[9];
    const float* Wo = (const float*)d_in[10];
    const float* bo = (const float*)d_in[11];
    const float* rel_table = (const float*)d_in[12];
    const float* gamma = (const float*)d_in[13];
    const float* beta  = (const float*)d_in[14];
    float* out = (float*)d_out;

    void *pQ, *pKXh, *pVXh, *pRK, *pAtt;
    cudaGetSymbolAddress(&pQ,   g_Q);
    cudaGetSymbolAddress(&pKXh, g_KXh);
    cudaGetSymbolAddress(&pVXh, g_VXh);
    cudaGetSymbolAddress(&pRK,  g_RK);
    cudaGetSymbolAddress(&pAtt, g_Att);

    detect_dtypes<<<1, 1024>>>((const int*)nidx, (const unsigned char*)mask);

    convert_prep<<<1064, 256>>>(ent, rel_table, Wq, Wk, Wv);

    gemm_tc<<<dim3(260, 3), 256>>>(bq, bk, bv,
                                   (float*)pQ, (__half*)pKXh, (__half*)pVXh, (float*)pRK);

    attn_kernel<<<M_NODES / 8, 256>>>(nidx, rids, mask);

    out_ln_kernel<<<M_NODES / 64, 256>>>((const float*)pAtt, Wo, bo, ent, gamma, beta, out);
}

// round 15
// speedup vs baseline: 1.9565x; 1.0665x over previous
#include <cuda_runtime.h>
#include <cuda_fp16.h>
#include <mma.h>
#include <math.h>

using namespace nvcuda;

#define M_NODES 16384
#define D_DIM   128
#define N_NBR   32
#define H_HEADS 8
#define DH_DIM  16
#define R_REL   237
#define R_PAD   256
#define LN_EPS  1e-5f
#define ATT_SCALE 0.25f   // 16^-0.5

// ---------------- scratch (static device globals; no allocs allowed) --------
__device__ float  g_Q  [M_NODES * D_DIM];
__device__ __half g_KXh[M_NODES * D_DIM];   // fp16 K table
__device__ __half g_VXh[M_NODES * D_DIM];   // fp16 V table
__device__ float  g_RK [R_REL   * D_DIM];   // fp32
__device__ __half g_Atth[M_NODES * D_DIM];  // fp16 attention output
__device__ __half g_Xh  [M_NODES * D_DIM];  // fp16 copy of entity_repr
__device__ __half g_relh[R_PAD  * D_DIM];   // fp16 rel_table (zero-padded)
__device__ __half g_Wqh[D_DIM * D_DIM];
__device__ __half g_Wkh[D_DIM * D_DIM];
__device__ __half g_Wvh[D_DIM * D_DIM];
__device__ __half g_Woh[D_DIM * D_DIM];
__device__ int    g_flags[2];   // [0]=indices are int64, [1]=mask is int32

// ---------------------------------------------------------------------------
// dtype probe: parallel over 1024 threads, block-wide OR reduction.
// ---------------------------------------------------------------------------
__global__ void detect_dtypes(const int* __restrict__ nidx_w,
                              const unsigned char* __restrict__ mask_b)
{
    const int t = threadIdx.x;
    int odd = 0, hi = 0;
    if (t < 256) odd = (nidx_w[2 * t + 1] != 0);
    if ((t & 3) != 0) hi = (mask_b[t] != 0);
    odd = __syncthreads_or(odd);
    hi  = __syncthreads_or(hi);
    if (t == 0) { g_flags[0] = !odd; g_flags[1] = !hi; }
}

// ---------------------------------------------------------------------------
// fp32 -> fp16 conversion prep. Each block converts 2048 elements.
// Segments: X (1024), rel padded (16), Wq (8), Wk (8), Wv (8), Wo (8).
// ---------------------------------------------------------------------------
__global__ __launch_bounds__(256) void convert_prep(
    const float* __restrict__ X, const float* __restrict__ rel,
    const float* __restrict__ Wq, const float* __restrict__ Wk,
    const float* __restrict__ Wv, const float* __restrict__ Wo)
{
    const int b = blockIdx.x;
    const int t = threadIdx.x;
    const float* src; __half* dst; size_t base, limit;
    if (b < 1024)      { src = X;   dst = g_Xh;   base = (size_t)b * 2048;          limit = (size_t)M_NODES * 128; }
    else if (b < 1040) { src = rel; dst = g_relh; base = (size_t)(b - 1024) * 2048; limit = (size_t)R_REL * 128; }
    else if (b < 1048) { src = Wq;  dst = g_Wqh;  base = (size_t)(b - 1040) * 2048; limit = 16384; }
    else if (b < 1056) { src = Wk;  dst = g_Wkh;  base = (size_t)(b - 1048) * 2048; limit = 16384; }
    else if (b < 1064) { src = Wv;  dst = g_Wvh;  base = (size_t)(b - 1056) * 2048; limit = 16384; }
    else               { src = Wo;  dst = g_Woh;  base = (size_t)(b - 1064) * 2048; limit = 16384; }

    size_t i = base + (size_t)t * 8;
    float v[8];
#pragma unroll
    for (int j = 0; j < 8; j++)
        v[j] = (i + j < limit) ? src[i + j] : 0.f;
    __half2 h0 = __floats2half2_rn(v[0], v[1]);
    __half2 h1 = __floats2half2_rn(v[2], v[3]);
    __half2 h2 = __floats2half2_rn(v[4], v[5]);
    __half2 h3 = __floats2half2_rn(v[6], v[7]);
    uint4 pk;
    pk.x = *reinterpret_cast<unsigned*>(&h0);
    pk.y = *reinterpret_cast<unsigned*>(&h1);
    pk.z = *reinterpret_cast<unsigned*>(&h2);
    pk.w = *reinterpret_cast<unsigned*>(&h3);
    *reinterpret_cast<uint4*>(dst + i) = pk;
}

// ---------------------------------------------------------------------------
// Tensor-core projection GEMM (wmma HMMA, fp16 in, fp32 accum).
// 64x128 tile per block, 8 warps (2 row x 4 col), 2x2 16^3 fragments each.
// grid = (260, 3):
//   y=0: Q = Xh@Wqh + bq (fp32) | y=1: KXh = Xh@Wkh (fp16), RK tail (fp32)
//   y=2: VXh = Xh@Wvh + bv (fp16)
// ---------------------------------------------------------------------------
__global__ __launch_bounds__(256) void gemm_tc(
    const float* __restrict__ bq, const float* __restrict__ bk,
    const float* __restrict__ bv,
    float* __restrict__ Q, __half* __restrict__ KXh,
    __half* __restrict__ VXh, float* __restrict__ RK)
{
    const int bx = blockIdx.x, by = blockIdx.y;
    const __half *A, *W;
    const float* bias;
    float*  OutF = 0;
    __half* OutH = 0;
    int rows, row0, half_out;
    if (by == 0) {
        if (bx >= 256) return;
        A = g_Xh; W = g_Wqh; bias = bq; OutF = Q; rows = M_NODES; row0 = bx * 64; half_out = 0;
    } else if (by == 2) {
        if (bx >= 256) return;
        A = g_Xh; W = g_Wvh; bias = bv; OutH = VXh; rows = M_NODES; row0 = bx * 64; half_out = 1;
    } else if (bx < 256) {
        A = g_Xh; W = g_Wkh; bias = 0; OutH = KXh; rows = M_NODES; row0 = bx * 64; half_out = 1;
    } else {
        A = g_relh; W = g_Wkh; bias = bk; OutF = RK; rows = R_REL; row0 = (bx - 256) * 64; half_out = 0;
    }

    __shared__ float sOut[64 * 136];

    const int warp = threadIdx.x >> 5;
    const int rw = warp >> 2;
    const int cw = warp & 3;

    wmma::fragment<wmma::accumulator, 16, 16, 16, float> c[2][2];
#pragma unroll
    for (int i = 0; i < 2; i++)
#pragma unroll
        for (int j = 0; j < 2; j++) wmma::fill_fragment(c[i][j], 0.f);

#pragma unroll
    for (int k = 0; k < 8; k++) {
        wmma::fragment<wmma::matrix_a, 16, 16, 16, __half, wmma::row_major> a[2];
        wmma::fragment<wmma::matrix_b, 16, 16, 16, __half, wmma::row_major> bfr[2];
#pragma unroll
        for (int i = 0; i < 2; i++)
            wmma::load_matrix_sync(a[i],
                A + (size_t)(row0 + rw * 32 + i * 16) * 128 + k * 16, 128);
#pragma unroll
        for (int j = 0; j < 2; j++)
            wmma::load_matrix_sync(bfr[j],
                W + (size_t)(k * 16) * 128 + cw * 32 + j * 16, 128);
#pragma unroll
        for (int i = 0; i < 2; i++)
#pragma unroll
            for (int j = 0; j < 2; j++)
                wmma::mma_sync(c[i][j], a[i], bfr[j], c[i][j]);
    }

#pragma unroll
    for (int i = 0; i < 2; i++)
#pragma unroll
        for (int j = 0; j < 2; j++)
            wmma::store_matrix_sync(
                sOut + (size_t)(rw * 32 + i * 16) * 136 + cw * 32 + j * 16,
                c[i][j], 136, wmma::mem_row_major);
    __syncthreads();

    {
        const int t = threadIdx.x;
        const int rl = t >> 2;
        const int c0 = (t & 3) * 32;
        const int r = row0 + rl;
        if (r < rows) {
            if (half_out) {
#pragma unroll
                for (int cc = 0; cc < 32; cc += 8) {
                    float o[8];
#pragma unroll
                    for (int u = 0; u < 8; u++) {
                        o[u] = sOut[rl * 136 + c0 + cc + u];
                        if (bias) o[u] += bias[c0 + cc + u];
                    }
                    __half2 h0 = __floats2half2_rn(o[0], o[1]);
                    __half2 h1 = __floats2half2_rn(o[2], o[3]);
                    __half2 h2 = __floats2half2_rn(o[4], o[5]);
                    __half2 h3 = __floats2half2_rn(o[6], o[7]);
                    uint4 pk;
                    pk.x = *reinterpret_cast<unsigned*>(&h0);
                    pk.y = *reinterpret_cast<unsigned*>(&h1);
                    pk.z = *reinterpret_cast<unsigned*>(&h2);
                    pk.w = *reinterpret_cast<unsigned*>(&h3);
                    *reinterpret_cast<uint4*>(OutH + (size_t)r * 128 + c0 + cc) = pk;
                }
            } else {
#pragma unroll
                for (int cc = 0; cc < 32; cc += 4) {
                    float o[4];
#pragma unroll
                    for (int u = 0; u < 4; u++) {
                        o[u] = sOut[rl * 136 + c0 + cc + u];
                        if (bias) o[u] += bias[c0 + cc + u];
                    }
                    *reinterpret_cast<float4*>(OutF + (size_t)r * 128 + c0 + cc)
                        = make_float4(o[0], o[1], o[2], o[3]);
                }
            }
        }
    }
}

// ---------------------------------------------------------------------------
// Attention: one WARP per node; masked neighbors compacted away (ballot+popc),
// warp-uniform count -> uniform early-exit loops at 4-granularity.
// Lane j owns dims [4j,4j+4). fp16 K/V gather; fp32 RK, Q; fp16 output.
// ---------------------------------------------------------------------------
__global__ __launch_bounds__(256) void attn_kernel(
    const void* __restrict__ nidx_v, const void* __restrict__ rids_v,
    const void* __restrict__ mask_v)
{
    __shared__ int s_idx[8][32];
    __shared__ int s_rel[8][32];

    const int warp = threadIdx.x >> 5;
    const int lane = threadIdx.x & 31;
    const int m = blockIdx.x * 8 + warp;

    int cnt;
    {
        size_t pos = (size_t)m * 32 + lane;
        const int idx64 = g_flags[0];
        const int msk32 = g_flags[1];
        int mk;
        if (msk32) mk = ((const int*)mask_v)[pos] != 0;
        else       mk = ((const unsigned char*)mask_v)[pos] != 0;
        int idx, rel;
        if (idx64) {
            idx = (int)((const long long*)nidx_v)[pos];
            rel = (int)((const long long*)rids_v)[pos];
        } else {
            idx = ((const int*)nidx_v)[pos];
            rel = ((const int*)rids_v)[pos];
        }
        const unsigned mb = __ballot_sync(0xffffffffu, mk);
        cnt = __popc(mb);
        int cpos = __popc(mb & ((1u << lane) - 1u));
        if (mk) { s_idx[warp][cpos] = idx; s_rel[warp][cpos] = rel; }
    }
    __syncwarp();

    const float4 q4 = *reinterpret_cast<const float4*>(g_Q + (size_t)m * 128 + lane * 4);

    float sc[32];
    float mx = -1e30f;
#pragma unroll
    for (int n0 = 0; n0 < 32; n0 += 4) {
        if (n0 >= cnt) break;
#pragma unroll
        for (int u = 0; u < 4; u++) {
            const int n = n0 + u;
            if (n < cnt) {
                uint2 kraw = *reinterpret_cast<const uint2*>(
                    g_KXh + (size_t)s_idx[warp][n] * 128 + lane * 4);
                float4 r4 = *reinterpret_cast<const float4*>(
                    g_RK + (size_t)s_rel[warp][n] * 128 + lane * 4);
                float2 k01 = __half22float2(*reinterpret_cast<__half2*>(&kraw.x));
                float2 k23 = __half22float2(*reinterpret_cast<__half2*>(&kraw.y));
                float p = q4.x * (k01.x + r4.x) + q4.y * (k01.y + r4.y)
                        + q4.z * (k23.x + r4.z) + q4.w * (k23.y + r4.w);
                p += __shfl_xor_sync(0xffffffffu, p, 1);
                p += __shfl_xor_sync(0xffffffffu, p, 2);
                sc[n] = p * ATT_SCALE;
                mx = fmaxf(mx, sc[n]);
            }
        }
    }

    float sum = 0.f;
#pragma unroll
    for (int n0 = 0; n0 < 32; n0 += 4) {
        if (n0 >= cnt) break;
#pragma unroll
        for (int u = 0; u < 4; u++) {
            const int n = n0 + u;
            if (n < cnt) {
                float e = __expf(sc[n] - mx);
                sc[n] = e;
                sum += e;
            }
        }
    }
    const float inv = 1.f / sum;

    float4 acc = make_float4(0.f, 0.f, 0.f, 0.f);
#pragma unroll
    for (int n0 = 0; n0 < 32; n0 += 4) {
        if (n0 >= cnt) break;
#pragma unroll
        for (int u = 0; u < 4; u++) {
            const int n = n0 + u;
            if (n < cnt) {
                float p = sc[n] * inv;
                uint2 vraw = *reinterpret_cast<const uint2*>(
                    g_VXh + (size_t)s_idx[warp][n] * 128 + lane * 4);
                float2 v01 = __half22float2(*reinterpret_cast<__half2*>(&vraw.x));
                float2 v23 = __half22float2(*reinterpret_cast<__half2*>(&vraw.y));
                acc.x = fmaf(p, v01.x, acc.x);
                acc.y = fmaf(p, v01.y, acc.y);
                acc.z = fmaf(p, v23.x, acc.z);
                acc.w = fmaf(p, v23.y, acc.w);
            }
        }
    }

    __half2 h0 = __floats2half2_rn(acc.x, acc.y);
    __half2 h1 = __floats2half2_rn(acc.z, acc.w);
    uint2 pk;
    pk.x = *reinterpret_cast<unsigned*>(&h0);
    pk.y = *reinterpret_cast<unsigned*>(&h1);
    *reinterpret_cast<uint2*>(g_Atth + (size_t)m * 128 + lane * 4) = pk;
}

// ---------------------------------------------------------------------------
// Out = LN(entity + Atth @ Woh + bo). Tensor-core GEMM (fp16 in, fp32 accum),
// 64x128 tile per block, LN epilogue with quad-shfl row reduction.
// ---------------------------------------------------------------------------
__global__ __launch_bounds__(256) void out_ln_tc(
    const float* __restrict__ bo, const float* __restrict__ ent,
    const float* __restrict__ gamma, const float* __restrict__ beta,
    float* __restrict__ Out)
{
    __shared__ float sOut[64 * 136];

    const int row0 = blockIdx.x * 64;
    const int warp = threadIdx.x >> 5;
    const int rw = warp >> 2;
    const int cw = warp & 3;

    wmma::fragment<wmma::accumulator, 16, 16, 16, float> c[2][2];
#pragma unroll
    for (int i = 0; i < 2; i++)
#pragma unroll
        for (int j = 0; j < 2; j++) wmma::fill_fragment(c[i][j], 0.f);

#pragma unroll
    for (int k = 0; k < 8; k++) {
        wmma::fragment<wmma::matrix_a, 16, 16, 16, __half, wmma::row_major> a[2];
        wmma::fragment<wmma::matrix_b, 16, 16, 16, __half, wmma::row_major> bfr[2];
#pragma unroll
        for (int i = 0; i < 2; i++)
            wmma::load_matrix_sync(a[i],
                g_Atth + (size_t)(row0 + rw * 32 + i * 16) * 128 + k * 16, 128);
#pragma unroll
        for (int j = 0; j < 2; j++)
            wmma::load_matrix_sync(bfr[j],
                g_Woh + (size_t)(k * 16) * 128 + cw * 32 + j * 16, 128);
#pragma unroll
        for (int i = 0; i < 2; i++)
#pragma unroll
            for (int j = 0; j < 2; j++)
                wmma::mma_sync(c[i][j], a[i], bfr[j], c[i][j]);
    }

#pragma unroll
    for (int i = 0; i < 2; i++)
#pragma unroll
        for (int j = 0; j < 2; j++)
            wmma::store_matrix_sync(
                sOut + (size_t)(rw * 32 + i * 16) * 136 + cw * 32 + j * 16,
                c[i][j], 136, wmma::mem_row_major);
    __syncthreads();

    // LN epilogue: thread t handles row rl = t>>2, cols [(t&3)*32, +32).
    const int t  = threadIdx.x;
    const int rl = t >> 2;
    const int c0 = (t & 3) * 32;
    const int r  = row0 + rl;

    float v[32];
    float s1 = 0.f, s2 = 0.f;
#pragma unroll
    for (int cc = 0; cc < 32; cc += 4) {
        float4 e4 = *reinterpret_cast<const float4*>(ent + (size_t)r * 128 + c0 + cc);
        float4 b4 = *reinterpret_cast<const float4*>(bo + c0 + cc);
        float vv[4] = {
            sOut[rl * 136 + c0 + cc + 0] + b4.x + e4.x,
            sOut[rl * 136 + c0 + cc + 1] + b4.y + e4.y,
            sOut[rl * 136 + c0 + cc + 2] + b4.z + e4.z,
            sOut[rl * 136 + c0 + cc + 3] + b4.w + e4.w };
#pragma unroll
        for (int u = 0; u < 4; u++) {
            v[cc + u] = vv[u];
            s1 += vv[u];
            s2 = fmaf(vv[u], vv[u], s2);
        }
    }
    s1 += __shfl_xor_sync(0xffffffffu, s1, 1);
    s1 += __shfl_xor_sync(0xffffffffu, s1, 2);
    s2 += __shfl_xor_sync(0xffffffffu, s2, 1);
    s2 += __shfl_xor_sync(0xffffffffu, s2, 2);

    const float mu   = s1 * (1.f / 128.f);
    const float var  = s2 * (1.f / 128.f) - mu * mu;
    const float rstd = rsqrtf(var + LN_EPS);

#pragma unroll
    for (int cc = 0; cc < 32; cc += 4) {
        float4 g4 = *reinterpret_cast<const float4*>(gamma + c0 + cc);
        float4 t4 = *reinterpret_cast<const float4*>(beta  + c0 + cc);
        float4 o;
        o.x = (v[cc + 0] - mu) * rstd * g4.x + t4.x;
        o.y = (v[cc + 1] - mu) * rstd * g4.y + t4.y;
        o.z = (v[cc + 2] - mu) * rstd * g4.z + t4.z;
        o.w = (v[cc + 3] - mu) * rstd * g4.w + t4.w;
        *reinterpret_cast<float4*>(Out + (size_t)r * 128 + c0 + cc) = o;
    }
}

// ---------------------------------------------------------------------------
extern "C" void kernel_launch(void* const* d_in, const int* in_sizes, int n_in,
                              void* d_out, int out_size)
{
    const float* ent  = (const float*)d_in[0];
    const void*  nidx = d_in[1];
    const void*  rids = d_in[2];
    const void*  mask = d_in[3];
    const float* Wq = (const float*)d_in[4];
    const float* bq = (const float*)d_in[5];
    const float* Wk = (const float*)d_in[6];
    const float* bk = (const float*)d_in[7];
    const float* Wv = (const float*)d_in[8];
    const float* bv = (const float*)d_in[9];
    const float* Wo = (const float*)d_in[10];
    const float* bo = (const float*)d_in[11];
    const float* rel_table = (const float*)d_in[12];
    const float* gamma = (const float*)d_in[13];
    const float* beta  = (const float*)d_in[14];
    float* out = (float*)d_out;

    void *pQ, *pKXh, *pVXh, *pRK;
    cudaGetSymbolAddress(&pQ,   g_Q);
    cudaGetSymbolAddress(&pKXh, g_KXh);
    cudaGetSymbolAddress(&pVXh, g_VXh);
    cudaGetSymbolAddress(&pRK,  g_RK);

    detect_dtypes<<<1, 1024>>>((const int*)nidx, (const unsigned char*)mask);

    convert_prep<<<1072, 256>>>(ent, rel_table, Wq, Wk, Wv, Wo);

    gemm_tc<<<dim3(260, 3), 256>>>(bq, bk, bv,
                                   (float*)pQ, (__half*)pKXh, (__half*)pVXh, (float*)pRK);

    attn_kernel<<<M_NODES / 8, 256>>>(nidx, rids, mask);

    out_ln_tc<<<M_NODES / 64, 256>>>(bo, ent, gamma, beta, out);
}

// round 17
// speedup vs baseline: 2.7708x; 1.4162x over previous
#include <cuda_runtime.h>
#include <cuda_fp16.h>
#include <mma.h>
#include <math.h>

using namespace nvcuda;

#define M_NODES 16384
#define D_DIM   128
#define N_NBR   32
#define H_HEADS 8
#define DH_DIM  16
#define R_REL   237
#define R_PAD   256
#define LN_EPS  1e-5f
#define ATT_SCALE 0.25f   // 16^-0.5

#define SPAD 136   // half-stride for smem tiles (128 + 8 pad, 16B aligned)

// ---------------- scratch (static device globals; no allocs allowed) --------
__device__ float  g_Q  [M_NODES * D_DIM];
__device__ __half g_KXh[M_NODES * D_DIM];   // fp16 K table
__device__ __half g_VXh[M_NODES * D_DIM];   // fp16 V table
__device__ float  g_RK [R_REL   * D_DIM];   // fp32
__device__ __half g_Atth[M_NODES * D_DIM];  // fp16 attention output
__device__ __half g_Xh  [M_NODES * D_DIM];  // fp16 copy of entity_repr
__device__ __half g_relh[R_PAD  * D_DIM];   // fp16 rel_table (zero-padded)
__device__ __half g_Wqh[D_DIM * D_DIM];
__device__ __half g_Wkh[D_DIM * D_DIM];
__device__ __half g_Wvh[D_DIM * D_DIM];
__device__ __half g_Woh[D_DIM * D_DIM];
__device__ int    g_flags[2];   // [0]=indices are int64, [1]=mask is int32

// ---------------------------------------------------------------------------
// fp32 -> fp16 conversion prep + dtype probe (block 1072).
// Blocks 0..1071 convert 2048 elements each:
//   X (1024), rel padded (16), Wq (8), Wk (8), Wv (8), Wo (8).
// ---------------------------------------------------------------------------
__global__ __launch_bounds__(256) void convert_prep(
    const float* __restrict__ X, const float* __restrict__ rel,
    const float* __restrict__ Wq, const float* __restrict__ Wk,
    const float* __restrict__ Wv, const float* __restrict__ Wo,
    const int* __restrict__ nidx_w, const unsigned char* __restrict__ mask_b)
{
    const int b = blockIdx.x;
    const int t = threadIdx.x;

    if (b == 1072) {   // dtype probe
        int odd = 0, hi = 0;
        if (t < 256) odd = (nidx_w[2 * t + 1] != 0);   // 256 odd-word checks
#pragma unroll
        for (int j = 0; j < 4; j++) {
            int byte = t * 4 + j;
            if ((byte & 3) != 0) hi |= (mask_b[byte] != 0);
        }
        odd = __syncthreads_or(odd);
        hi  = __syncthreads_or(hi);
        if (t == 0) { g_flags[0] = !odd; g_flags[1] = !hi; }
        return;
    }

    const float* src; __half* dst; size_t base, limit;
    if (b < 1024)      { src = X;   dst = g_Xh;   base = (size_t)b * 2048;          limit = (size_t)M_NODES * 128; }
    else if (b < 1040) { src = rel; dst = g_relh; base = (size_t)(b - 1024) * 2048; limit = (size_t)R_REL * 128; }
    else if (b < 1048) { src = Wq;  dst = g_Wqh;  base = (size_t)(b - 1040) * 2048; limit = 16384; }
    else if (b < 1056) { src = Wk;  dst = g_Wkh;  base = (size_t)(b - 1048) * 2048; limit = 16384; }
    else if (b < 1064) { src = Wv;  dst = g_Wvh;  base = (size_t)(b - 1056) * 2048; limit = 16384; }
    else               { src = Wo;  dst = g_Woh;  base = (size_t)(b - 1064) * 2048; limit = 16384; }

    size_t i = base + (size_t)t * 8;
    float v[8];
#pragma unroll
    for (int j = 0; j < 8; j++)
        v[j] = (i + j < limit) ? src[i + j] : 0.f;
    __half2 h0 = __floats2half2_rn(v[0], v[1]);
    __half2 h1 = __floats2half2_rn(v[2], v[3]);
    __half2 h2 = __floats2half2_rn(v[4], v[5]);
    __half2 h3 = __floats2half2_rn(v[6], v[7]);
    uint4 pk;
    pk.x = *reinterpret_cast<unsigned*>(&h0);
    pk.y = *reinterpret_cast<unsigned*>(&h1);
    pk.z = *reinterpret_cast<unsigned*>(&h2);
    pk.w = *reinterpret_cast<unsigned*>(&h3);
    *reinterpret_cast<uint4*>(dst + i) = pk;
}

// ---------------------------------------------------------------------------
// Shared helpers for smem-staged wmma GEMM (64x128 tile, 256 thr, 8 warps).
// sA: 64x128 fp16 (stride SPAD), sW: 64x128 k-chunk (stride SPAD), sOut: union.
// ---------------------------------------------------------------------------
#define SMEM_BYTES 34816   // = max(sA+sW, sOut) = 2*64*136*2 = 64*136*4

__device__ __forceinline__ void load_tile64(
    __half* dstS, const __half* __restrict__ src, int src_row0)
{
    const int tid = threadIdx.x;
#pragma unroll
    for (int it = 0; it < 4; it++) {
        int i = tid + it * 256;          // 0..1023 uint4 slots
        int r = i >> 4, q = i & 15;      // 64 rows x 16 uint4
        uint4 v = *reinterpret_cast<const uint4*>(src + (size_t)(src_row0 + r) * 128 + q * 8);
        *reinterpret_cast<uint4*>(dstS + r * SPAD + q * 8) = v;
    }
}

// ---------------------------------------------------------------------------
// Tensor-core projection GEMM (smem-staged wmma, fp16 in, fp32 accum).
// grid = (260, 3):
//   y=0: Q = Xh@Wqh + bq (fp32) | y=1: KXh = Xh@Wkh (fp16), RK tail (fp32)
//   y=2: VXh = Xh@Wvh + bv (fp16)
// ---------------------------------------------------------------------------
__global__ __launch_bounds__(256) void gemm_tc(
    const float* __restrict__ bq, const float* __restrict__ bk,
    const float* __restrict__ bv,
    float* __restrict__ Q, __half* __restrict__ KXh,
    __half* __restrict__ VXh, float* __restrict__ RK)
{
    const int bx = blockIdx.x, by = blockIdx.y;
    const __half *A, *W;
    const float* bias;
    float*  OutF = 0;
    __half* OutH = 0;
    int rows, row0, half_out;
    if (by == 0) {
        if (bx >= 256) return;
        A = g_Xh; W = g_Wqh; bias = bq; OutF = Q; rows = M_NODES; row0 = bx * 64; half_out = 0;
    } else if (by == 2) {
        if (bx >= 256) return;
        A = g_Xh; W = g_Wvh; bias = bv; OutH = VXh; rows = M_NODES; row0 = bx * 64; half_out = 1;
    } else if (bx < 256) {
        A = g_Xh; W = g_Wkh; bias = 0; OutH = KXh; rows = M_NODES; row0 = bx * 64; half_out = 1;
    } else {
        A = g_relh; W = g_Wkh; bias = bk; OutF = RK; rows = R_REL; row0 = (bx - 256) * 64; half_out = 0;
    }

    __shared__ __align__(16) unsigned char smem_raw[SMEM_BYTES];
    __half* sA   = reinterpret_cast<__half*>(smem_raw);            // 64 x SPAD
    __half* sW   = reinterpret_cast<__half*>(smem_raw + 17408);    // 64 x SPAD
    float*  sOut = reinterpret_cast<float*>(smem_raw);             // 64 x SPAD

    const int warp = threadIdx.x >> 5;
    const int rw = warp >> 2;
    const int cw = warp & 3;

    wmma::fragment<wmma::accumulator, 16, 16, 16, float> c[2][2];
#pragma unroll
    for (int i = 0; i < 2; i++)
#pragma unroll
        for (int j = 0; j < 2; j++) wmma::fill_fragment(c[i][j], 0.f);

    load_tile64(sA, A, row0);   // A tile: 64 rows (g_relh padded to 256, no OOB)

#pragma unroll
    for (int kc = 0; kc < 2; kc++) {
        if (kc > 0) __syncthreads();       // all warps done reading prev sW
        load_tile64(sW, W, kc * 64);       // W k-chunk: rows kc*64..+64
        __syncthreads();
#pragma unroll
        for (int kk = 0; kk < 4; kk++) {
            wmma::fragment<wmma::matrix_a, 16, 16, 16, __half, wmma::row_major> a[2];
            wmma::fragment<wmma::matrix_b, 16, 16, 16, __half, wmma::row_major> bfr[2];
#pragma unroll
            for (int i = 0; i < 2; i++)
                wmma::load_matrix_sync(a[i],
                    sA + (rw * 32 + i * 16) * SPAD + kc * 64 + kk * 16, SPAD);
#pragma unroll
            for (int j = 0; j < 2; j++)
                wmma::load_matrix_sync(bfr[j],
                    sW + (kk * 16) * SPAD + cw * 32 + j * 16, SPAD);
#pragma unroll
            for (int i = 0; i < 2; i++)
#pragma unroll
                for (int j = 0; j < 2; j++)
                    wmma::mma_sync(c[i][j], a[i], bfr[j], c[i][j]);
        }
    }

    __syncthreads();   // before overwriting sA/sW with sOut
#pragma unroll
    for (int i = 0; i < 2; i++)
#pragma unroll
        for (int j = 0; j < 2; j++)
            wmma::store_matrix_sync(
                sOut + (rw * 32 + i * 16) * SPAD + cw * 32 + j * 16,
                c[i][j], SPAD, wmma::mem_row_major);
    __syncthreads();

    {
        const int t = threadIdx.x;
        const int rl = t >> 2;
        const int c0 = (t & 3) * 32;
        const int r = row0 + rl;
        if (r < rows) {
            if (half_out) {
#pragma unroll
                for (int cc = 0; cc < 32; cc += 8) {
                    float o[8];
#pragma unroll
                    for (int u = 0; u < 8; u++) {
                        o[u] = sOut[rl * SPAD + c0 + cc + u];
                        if (bias) o[u] += bias[c0 + cc + u];
                    }
                    __half2 h0 = __floats2half2_rn(o[0], o[1]);
                    __half2 h1 = __floats2half2_rn(o[2], o[3]);
                    __half2 h2 = __floats2half2_rn(o[4], o[5]);
                    __half2 h3 = __floats2half2_rn(o[6], o[7]);
                    uint4 pk;
                    pk.x = *reinterpret_cast<unsigned*>(&h0);
                    pk.y = *reinterpret_cast<unsigned*>(&h1);
                    pk.z = *reinterpret_cast<unsigned*>(&h2);
                    pk.w = *reinterpret_cast<unsigned*>(&h3);
                    *reinterpret_cast<uint4*>(OutH + (size_t)r * 128 + c0 + cc) = pk;
                }
            } else {
#pragma unroll
                for (int cc = 0; cc < 32; cc += 4) {
                    float o[4];
#pragma unroll
                    for (int u = 0; u < 4; u++) {
                        o[u] = sOut[rl * SPAD + c0 + cc + u];
                        if (bias) o[u] += bias[c0 + cc + u];
                    }
                    *reinterpret_cast<float4*>(OutF + (size_t)r * 128 + c0 + cc)
                        = make_float4(o[0], o[1], o[2], o[3]);
                }
            }
        }
    }
}

// ---------------------------------------------------------------------------
// Attention: one WARP per node; masked neighbors compacted away (ballot+popc),
// warp-uniform count -> uniform early-exit loops at 4-granularity.
// Lane j owns dims [4j,4j+4). fp16 K/V gather; fp32 RK, Q; fp16 output.
// ---------------------------------------------------------------------------
__global__ __launch_bounds__(256) void attn_kernel(
    const void* __restrict__ nidx_v, const void* __restrict__ rids_v,
    const void* __restrict__ mask_v)
{
    __shared__ int s_idx[8][32];
    __shared__ int s_rel[8][32];

    const int warp = threadIdx.x >> 5;
    const int lane = threadIdx.x & 31;
    const int m = blockIdx.x * 8 + warp;

    int cnt;
    {
        size_t pos = (size_t)m * 32 + lane;
        const int idx64 = g_flags[0];
        const int msk32 = g_flags[1];
        int mk;
        if (msk32) mk = ((const int*)mask_v)[pos] != 0;
        else       mk = ((const unsigned char*)mask_v)[pos] != 0;
        int idx, rel;
        if (idx64) {
            idx = (int)((const long long*)nidx_v)[pos];
            rel = (int)((const long long*)rids_v)[pos];
        } else {
            idx = ((const int*)nidx_v)[pos];
            rel = ((const int*)rids_v)[pos];
        }
        const unsigned mb = __ballot_sync(0xffffffffu, mk);
        cnt = __popc(mb);
        int cpos = __popc(mb & ((1u << lane) - 1u));
        if (mk) { s_idx[warp][cpos] = idx; s_rel[warp][cpos] = rel; }
    }
    __syncwarp();

    const float4 q4 = *reinterpret_cast<const float4*>(g_Q + (size_t)m * 128 + lane * 4);

    float sc[32];
    float mx = -1e30f;
#pragma unroll
    for (int n0 = 0; n0 < 32; n0 += 4) {
        if (n0 >= cnt) break;
#pragma unroll
        for (int u = 0; u < 4; u++) {
            const int n = n0 + u;
            if (n < cnt) {
                uint2 kraw = *reinterpret_cast<const uint2*>(
                    g_KXh + (size_t)s_idx[warp][n] * 128 + lane * 4);
                float4 r4 = *reinterpret_cast<const float4*>(
                    g_RK + (size_t)s_rel[warp][n] * 128 + lane * 4);
                float2 k01 = __half22float2(*reinterpret_cast<__half2*>(&kraw.x));
                float2 k23 = __half22float2(*reinterpret_cast<__half2*>(&kraw.y));
                float p = q4.x * (k01.x + r4.x) + q4.y * (k01.y + r4.y)
                        + q4.z * (k23.x + r4.z) + q4.w * (k23.y + r4.w);
                p += __shfl_xor_sync(0xffffffffu, p, 1);
                p += __shfl_xor_sync(0xffffffffu, p, 2);
                sc[n] = p * ATT_SCALE;
                mx = fmaxf(mx, sc[n]);
            }
        }
    }

    float sum = 0.f;
#pragma unroll
    for (int n0 = 0; n0 < 32; n0 += 4) {
        if (n0 >= cnt) break;
#pragma unroll
        for (int u = 0; u < 4; u++) {
            const int n = n0 + u;
            if (n < cnt) {
                float e = __expf(sc[n] - mx);
                sc[n] = e;
                sum += e;
            }
        }
    }
    const float inv = 1.f / sum;

    float4 acc = make_float4(0.f, 0.f, 0.f, 0.f);
#pragma unroll
    for (int n0 = 0; n0 < 32; n0 += 4) {
        if (n0 >= cnt) break;
#pragma unroll
        for (int u = 0; u < 4; u++) {
            const int n = n0 + u;
            if (n < cnt) {
                float p = sc[n] * inv;
                uint2 vraw = *reinterpret_cast<const uint2*>(
                    g_VXh + (size_t)s_idx[warp][n] * 128 + lane * 4);
                float2 v01 = __half22float2(*reinterpret_cast<__half2*>(&vraw.x));
                float2 v23 = __half22float2(*reinterpret_cast<__half2*>(&vraw.y));
                acc.x = fmaf(p, v01.x, acc.x);
                acc.y = fmaf(p, v01.y, acc.y);
                acc.z = fmaf(p, v23.x, acc.z);
                acc.w = fmaf(p, v23.y, acc.w);
            }
        }
    }

    __half2 h0 = __floats2half2_rn(acc.x, acc.y);
    __half2 h1 = __floats2half2_rn(acc.z, acc.w);
    uint2 pk;
    pk.x = *reinterpret_cast<unsigned*>(&h0);
    pk.y = *reinterpret_cast<unsigned*>(&h1);
    *reinterpret_cast<uint2*>(g_Atth + (size_t)m * 128 + lane * 4) = pk;
}

// ---------------------------------------------------------------------------
// Out = LN(entity + Atth @ Woh + bo). Smem-staged wmma GEMM + LN epilogue
// with quad-shfl row reduction.
// ---------------------------------------------------------------------------
__global__ __launch_bounds__(256) void out_ln_tc(
    const float* __restrict__ bo, const float* __restrict__ ent,
    const float* __restrict__ gamma, const float* __restrict__ beta,
    float* __restrict__ Out)
{
    __shared__ __align__(16) unsigned char smem_raw[SMEM_BYTES];
    __half* sA   = reinterpret_cast<__half*>(smem_raw);
    __half* sW   = reinterpret_cast<__half*>(smem_raw + 17408);
    float*  sOut = reinterpret_cast<float*>(smem_raw);

    const int row0 = blockIdx.x * 64;
    const int warp = threadIdx.x >> 5;
    const int rw = warp >> 2;
    const int cw = warp & 3;

    wmma::fragment<wmma::accumulator, 16, 16, 16, float> c[2][2];
#pragma unroll
    for (int i = 0; i < 2; i++)
#pragma unroll
        for (int j = 0; j < 2; j++) wmma::fill_fragment(c[i][j], 0.f);

    load_tile64(sA, g_Atth, row0);

#pragma unroll
    for (int kc = 0; kc < 2; kc++) {
        if (kc > 0) __syncthreads();
        load_tile64(sW, g_Woh, kc * 64);
        __syncthreads();
#pragma unroll
        for (int kk = 0; kk < 4; kk++) {
            wmma::fragment<wmma::matrix_a, 16, 16, 16, __half, wmma::row_major> a[2];
            wmma::fragment<wmma::matrix_b, 16, 16, 16, __half, wmma::row_major> bfr[2];
#pragma unroll
            for (int i = 0; i < 2; i++)
                wmma::load_matrix_sync(a[i],
                    sA + (rw * 32 + i * 16) * SPAD + kc * 64 + kk * 16, SPAD);
#pragma unroll
            for (int j = 0; j < 2; j++)
                wmma::load_matrix_sync(bfr[j],
                    sW + (kk * 16) * SPAD + cw * 32 + j * 16, SPAD);
#pragma unroll
            for (int i = 0; i < 2; i++)
#pragma unroll
                for (int j = 0; j < 2; j++)
                    wmma::mma_sync(c[i][j], a[i], bfr[j], c[i][j]);
        }
    }

    __syncthreads();
#pragma unroll
    for (int i = 0; i < 2; i++)
#pragma unroll
        for (int j = 0; j < 2; j++)
            wmma::store_matrix_sync(
                sOut + (rw * 32 + i * 16) * SPAD + cw * 32 + j * 16,
                c[i][j], SPAD, wmma::mem_row_major);
    __syncthreads();

    // LN epilogue: thread t handles row rl = t>>2, cols [(t&3)*32, +32).
    const int t  = threadIdx.x;
    const int rl = t >> 2;
    const int c0 = (t & 3) * 32;
    const int r  = row0 + rl;

    float v[32];
    float s1 = 0.f, s2 = 0.f;
#pragma unroll
    for (int cc = 0; cc < 32; cc += 4) {
        float4 e4 = *reinterpret_cast<const float4*>(ent + (size_t)r * 128 + c0 + cc);
        float4 b4 = *reinterpret_cast<const float4*>(bo + c0 + cc);
        float vv[4] = {
            sOut[rl * SPAD + c0 + cc + 0] + b4.x + e4.x,
            sOut[rl * SPAD + c0 + cc + 1] + b4.y + e4.y,
            sOut[rl * SPAD + c0 + cc + 2] + b4.z + e4.z,
            sOut[rl * SPAD + c0 + cc + 3] + b4.w + e4.w };
#pragma unroll
        for (int u = 0; u < 4; u++) {
            v[cc + u] = vv[u];
            s1 += vv[u];
            s2 = fmaf(vv[u], vv[u], s2);
        }
    }
    s1 += __shfl_xor_sync(0xffffffffu, s1, 1);
    s1 += __shfl_xor_sync(0xffffffffu, s1, 2);
    s2 += __shfl_xor_sync(0xffffffffu, s2, 1);
    s2 += __shfl_xor_sync(0xffffffffu, s2, 2);

    const float mu   = s1 * (1.f / 128.f);
    const float var  = s2 * (1.f / 128.f) - mu * mu;
    const float rstd = rsqrtf(var + LN_EPS);

#pragma unroll
    for (int cc = 0; cc < 32; cc += 4) {
        float4 g4 = *reinterpret_cast<const float4*>(gamma + c0 + cc);
        float4 t4 = *reinterpret_cast<const float4*>(beta  + c0 + cc);
        float4 o;
        o.x = (v[cc + 0] - mu) * rstd * g4.x + t4.x;
        o.y = (v[cc + 1] - mu) * rstd * g4.y + t4.y;
        o.z = (v[cc + 2] - mu) * rstd * g4.z + t4.z;
        o.w = (v[cc + 3] - mu) * rstd * g4.w + t4.w;
        *reinterpret_cast<float4*>(Out + (size_t)r * 128 + c0 + cc) = o;
    }
}

// ---------------------------------------------------------------------------
extern "C" void kernel_launch(void* const* d_in, const int* in_sizes, int n_in,
                              void* d_out, int out_size)
{
    const float* ent  = (const float*)d_in[0];
    const void*  nidx = d_in[1];
    const void*  rids = d_in[2];
    const void*  mask = d_in[3];
    const float* Wq = (const float*)d_in[4];
    const float* bq = (const float*)d_in[5];
    const float* Wk = (const float*)d_in[6];
    const float* bk = (const float*)d_in[7];
    const float* Wv = (const float*)d_in[8];
    const float* bv = (const float*)d_in[9];
    const float* Wo = (const float*)d_in[10];
    const float* bo = (const float*)d_in[11];
    const float* rel_table = (const float*)d_in[12];
    const float* gamma = (const float*)d_in[13];
    const float* beta  = (const float*)d_in[14];
    float* out = (float*)d_out;

    void *pQ, *pKXh, *pVXh, *pRK;
    cudaGetSymbolAddress(&pQ,   g_Q);
    cudaGetSymbolAddress(&pKXh, g_KXh);
    cudaGetSymbolAddress(&pVXh, g_VXh);
    cudaGetSymbolAddress(&pRK,  g_RK);

    convert_prep<<<1073, 256>>>(ent, rel_table, Wq, Wk, Wv, Wo,
                                (const int*)nidx, (const unsigned char*)mask);

    gemm_tc<<<dim3(260, 3), 256>>>(bq, bk, bv,
                                   (float*)pQ, (__half*)pKXh, (__half*)pVXh, (float*)pRK);

    attn_kernel<<<M_NODES / 8, 256>>>(nidx, rids, mask);

    out_ln_tc<<<M_NODES / 64, 256>>>(bo, ent, gamma, beta, out);
}